// round 9
// baseline (speedup 1.0000x reference)
#include <cuda_runtime.h>
#include <cuda_bf16.h>

// ---------------------------------------------------------------------------
// CutsSelector collapsed to scalar-per-node form:
//   v = f2@cls ; u = f1@cls ; p = Wd@v ; q = Ws@v
//   r = we.v ; s = g_b.v ; c0 = f_b.cls + cls_b
//   t[n]=x[n].q ; du[n]=x[n].u ; dp[n]=x[n].p
//   per edge: acc64[rep][dst] += enc(t[src] + r*ea)  (ONE u64 L2 red, exact
//     fixed point: bits 0..51 value-sum, bits 52..63 count; 4 replicas)
//   score = du + c0 + (cnt>0 ? dp + sum_v/cnt + s : 0) ; probs = sigmoid
//
// TWO launches:
//   K_setup (32 x 256, 1 internal barrier): matvecs + scalars + zero acc.
//   K_main  (296 x 1024, smem = N*4, 2 barriers): t/du/dp -> stage t in SMEM
//           -> 4-edges-per-thread u64 reds -> decode + output.
// R8 bug fixed: all arrays accessed through float4/longlong2 casts are now
// explicitly 16-byte aligned (shared svec was at offset 4 after an int).
// ---------------------------------------------------------------------------

#define C 128
#define NODE_CAP 24576
#define NREP 4
#define SU_NBLK 32
#define SU_NTHR 256
#define MB_NBLK 296
#define MB_NTHR 1024

#define ENC_OFFSET 4096
#define ENC_SCALE  262144.0f          /* 2^18 */
#define ENC_INV    (1.0f / 262144.0f)
#define CNT_SHIFT  52

__device__ __align__(16) float  g_vec_u[C];
__device__ __align__(16) float  g_vec_v[C];
__device__ __align__(16) float  g_vec_p[C];
__device__ __align__(16) float  g_vec_q[C];
__device__ float  g_scalar_r;
__device__ float  g_scalar_s;
__device__ float  g_scalar_c0;
__device__ __align__(16) float  g_t[NODE_CAP];
__device__ __align__(16) float2 g_ddp[NODE_CAP];        // {du, dp}
__device__ __align__(16) unsigned long long g_acc64[NREP * NODE_CAP];
__device__ unsigned g_bar0, g_done0;                    // setup barrier
__device__ unsigned g_bar1, g_done1;                    // main barriers

__device__ __forceinline__ float warp_sum(float v) {
    #pragma unroll
    for (int o = 16; o > 0; o >>= 1) v += __shfl_xor_sync(0xffffffffu, v, o);
    return v;
}

// Exact fixed-point edge encoding (validated R5-R7, rel_err 1.25e-7):
// integer part (vi+4096)<<18, fraction round-to-nearest at 2^-18, +1 in count.
__device__ __forceinline__ unsigned long long enc_edge(float v) {
    int   vi  = __float2int_rn(v);
    float fr  = v - (float)vi;                   // exact, |fr| <= 0.5
    int   fri = __float2int_rn(fr * ENC_SCALE);  // exact product (2^18)
    return ((unsigned long long)(unsigned)(vi + ENC_OFFSET) << 18)
         + (unsigned long long)(long long)fri
         + (1ULL << CNT_SHIFT);
}

__device__ __forceinline__ void red_u64(unsigned long long* p,
                                        unsigned long long v) {
    asm volatile("red.global.add.u64 [%0], %1;" :: "l"(p), "l"(v) : "memory");
}

__device__ __forceinline__ void spin_barrier(unsigned* bar, unsigned target) {
    __syncthreads();
    if (threadIdx.x == 0) {
        __threadfence();
        atomicAdd(bar, 1u);
        unsigned v;
        do {
            asm volatile("ld.global.acquire.gpu.u32 %0, [%1];"
                         : "=r"(v) : "l"(bar));
        } while (v < target);
    }
    __syncthreads();
}

// ============================ K_setup =======================================
__global__ void __launch_bounds__(SU_NTHR, 1)
setup_kernel(const float* __restrict__ g_w,   // [257,128]
             const float* __restrict__ g_b,   // [128]
             const float* __restrict__ f_w,   // [256,128]
             const float* __restrict__ f_b,   // [128]
             const float* __restrict__ cls_w, // [128]
             const float* __restrict__ cls_b) // [1]
{
    const int tid  = threadIdx.x;
    const int bid  = blockIdx.x;
    const int wi   = tid >> 5;
    const int lane = tid & 31;
    const int gwarp = bid * (SU_NTHR / 32) + wi;   // 0..255

    // Stage 1: f_w row `gwarp` dot cls_w -> u (0..127) / v (128..255)
    {
        float4 cc = __ldg((const float4*)cls_w + lane);
        float4 a  = __ldg((const float4*)(f_w + (size_t)gwarp * C) + lane);
        float part = warp_sum(a.x * cc.x + a.y * cc.y + a.z * cc.z + a.w * cc.w);
        if (lane == 0) {
            if (gwarp < C) g_vec_u[gwarp] = part;
            else           g_vec_v[gwarp - C] = part;
        }
    }

    // Zero accumulator replicas while stage-1 latency drains.
    for (int i = bid * SU_NTHR + tid; i < NREP * NODE_CAP; i += SU_NBLK * SU_NTHR)
        g_acc64[i] = 0ULL;

    spin_barrier(&g_bar0, (unsigned)gridDim.x);

    // Stage 2: g_w row `gwarp` dot v -> p (0..127) / q (128..255)
    {
        float4 vv = *((const float4*)g_vec_v + lane);   // L2-hot
        float4 a  = __ldg((const float4*)(g_w + (size_t)gwarp * C) + lane);
        float part = warp_sum(a.x * vv.x + a.y * vv.y + a.z * vv.z + a.w * vv.w);
        if (lane == 0) {
            if (gwarp < C) g_vec_p[gwarp]     = part;
            else           g_vec_q[gwarp - C] = part;
        }
    }

    // Scalars (block 0, warp 0)
    if (bid == 0 && wi == 0) {
        float r = 0.f, s = 0.f, c = 0.f;
        #pragma unroll
        for (int k = lane; k < C; k += 32) {
            float vk = g_vec_v[k];
            r += __ldg(&g_w[2 * C * C + k]) * vk;
            s += __ldg(&g_b[k]) * vk;
            c += __ldg(&f_b[k]) * __ldg(&cls_w[k]);
        }
        r = warp_sum(r); s = warp_sum(s); c = warp_sum(c);
        if (lane == 0) {
            g_scalar_r  = r;
            g_scalar_s  = s;
            g_scalar_c0 = c + __ldg(&cls_b[0]);
        }
    }

    // Self-reset for graph replay.
    __syncthreads();
    if (tid == 0) {
        __threadfence();
        unsigned old = atomicAdd(&g_done0, 1u);
        if (old == (unsigned)gridDim.x - 1u) {
            g_bar0 = 0u; g_done0 = 0u;
            __threadfence();
        }
    }
}

// ============================ K_main ========================================
__global__ void __launch_bounds__(MB_NTHR, 2)
main_kernel(const float* __restrict__ x,
            const void*  __restrict__ eidx,
            const float* __restrict__ ea,
            float* __restrict__ out,
            int N, long long E, int twopart)
{
    extern __shared__ __align__(16) float st[];   // staged t table, N floats
    const int tid  = threadIdx.x;
    const int bid  = blockIdx.x;
    const int nblk = gridDim.x;
    const int wi   = tid >> 5;
    const int lane = tid & 31;
    const long long gtid       = (long long)bid * MB_NTHR + tid;
    const long long totThreads = (long long)nblk * MB_NTHR;

    __shared__ __align__(16) float svec[3 * C];   // q | u | p  (16B aligned!)
    __shared__ int s_is64;

    // index-dtype sniff: int64 nonneg < 2^31 shows zeros at odd int32 slots
    if (tid < 32) {
        const int* p = (const int*)eidx;
        int ok = (p[2 * tid + 1] == 0) &&
                 (p[2 * (tid + 32) + 1] == 0) &&
                 (p[2 * (tid + 64) + 1] == 0);
        unsigned b = __ballot_sync(0xffffffffu, ok);
        if (tid == 0) s_is64 = (b == 0xffffffffu) ? 1 : 0;
    }
    if (tid < C) {
        svec[tid]         = g_vec_q[tid];
        svec[C + tid]     = g_vec_u[tid];
        svec[2 * C + tid] = g_vec_p[tid];
    }
    __syncthreads();

    // ---- phase 1: t / du / dp (warp per node, strided) ----
    {
        float4 qv = ((const float4*)svec)[lane];
        float4 uv = ((const float4*)(svec + C))[lane];
        float4 pv = ((const float4*)(svec + 2 * C))[lane];
        const int totalWarps = nblk * (MB_NTHR / 32);
        for (int node = bid * (MB_NTHR / 32) + wi; node < N; node += totalWarps) {
            float4 xv = __ldg((const float4*)(x + (size_t)node * C) + lane);
            float dq = xv.x * qv.x + xv.y * qv.y + xv.z * qv.z + xv.w * qv.w;
            float du = xv.x * uv.x + xv.y * uv.y + xv.z * uv.z + xv.w * uv.w;
            float dp = xv.x * pv.x + xv.y * pv.y + xv.z * pv.z + xv.w * pv.w;
            #pragma unroll
            for (int o = 16; o > 0; o >>= 1) {
                dq += __shfl_xor_sync(0xffffffffu, dq, o);
                du += __shfl_xor_sync(0xffffffffu, du, o);
                dp += __shfl_xor_sync(0xffffffffu, dp, o);
            }
            if (lane == 0) {
                g_t[node]   = dq;
                g_ddp[node] = make_float2(du, dp);
            }
        }
    }

    spin_barrier(&g_bar1, (unsigned)nblk);

    // ---- stage t into SMEM (coalesced) ----
    {
        const int n4 = N >> 2;
        const float4* t4 = (const float4*)g_t;
        float4* s4 = (float4*)st;
        for (int i = tid; i < n4; i += MB_NTHR) s4[i] = t4[i];
        for (int i = (n4 << 2) + tid; i < N; i += MB_NTHR) st[i] = g_t[i];
    }
    __syncthreads();

    // ---- phase 2: edges, 4 per thread, contiguous quads, single pass ----
    {
        const float rs = g_scalar_r;
        unsigned long long* acc = g_acc64 + (size_t)(bid & (NREP - 1)) * NODE_CAP;
        const long long quads = E >> 2;
        if (s_is64) {
            const longlong2* ps = (const longlong2*)eidx;
            const longlong2* pd = (const longlong2*)((const long long*)eidx + E);
            const float4*    a4 = (const float4*)ea;
            for (long long j = gtid; j < quads; j += totThreads) {
                longlong2 s01 = ps[2 * j];
                longlong2 s23 = ps[2 * j + 1];
                longlong2 d01 = pd[2 * j];
                longlong2 d23 = pd[2 * j + 1];
                float4    e4  = a4[j];
                float v0 = st[s01.x] + e4.x * rs;
                float v1 = st[s01.y] + e4.y * rs;
                float v2 = st[s23.x] + e4.z * rs;
                float v3 = st[s23.y] + e4.w * rs;
                red_u64(&acc[d01.x], enc_edge(v0));
                red_u64(&acc[d01.y], enc_edge(v1));
                red_u64(&acc[d23.x], enc_edge(v2));
                red_u64(&acc[d23.y], enc_edge(v3));
            }
            if (gtid == 0) {
                const long long* p = (const long long*)eidx;
                for (long long e = quads << 2; e < E; e++) {
                    float v = st[p[e]] + ea[e] * rs;
                    red_u64(&acc[p[E + e]], enc_edge(v));
                }
            }
        } else {
            const int4*   ps = (const int4*)eidx;
            const int4*   pd = (const int4*)((const int*)eidx + E);
            const float4* a4 = (const float4*)ea;
            for (long long j = gtid; j < quads; j += totThreads) {
                int4   s4 = ps[j];
                int4   d4 = pd[j];
                float4 e4 = a4[j];
                float v0 = st[s4.x] + e4.x * rs;
                float v1 = st[s4.y] + e4.y * rs;
                float v2 = st[s4.z] + e4.z * rs;
                float v3 = st[s4.w] + e4.w * rs;
                red_u64(&acc[d4.x], enc_edge(v0));
                red_u64(&acc[d4.y], enc_edge(v1));
                red_u64(&acc[d4.z], enc_edge(v2));
                red_u64(&acc[d4.w], enc_edge(v3));
            }
            if (gtid == 0) {
                const int* p = (const int*)eidx;
                for (long long e = quads << 2; e < E; e++) {
                    float v = st[p[e]] + ea[e] * rs;
                    red_u64(&acc[p[E + e]], enc_edge(v));
                }
            }
        }
    }

    spin_barrier(&g_bar1, 2u * (unsigned)nblk);

    // ---- phase 3: decode (sum replicas) + output ----
    {
        const float ss = g_scalar_s;
        const float c0 = g_scalar_c0;
        for (long long n = gtid; n < N; n += totThreads) {
            unsigned long long acc = g_acc64[n]
                                   + g_acc64[NODE_CAP + n]
                                   + g_acc64[2 * NODE_CAP + n]
                                   + g_acc64[3 * NODE_CAP + n];
            unsigned cnt = (unsigned)(acc >> CNT_SHIFT);
            unsigned long long raw = acc & ((1ULL << CNT_SHIFT) - 1ULL);
            float2 ddp = g_ddp[n];
            float score = ddp.x + c0;
            if (cnt > 0u) {
                // hi, lo and 4096*cnt are exact integers < 2^24 in fp32.
                float hi = (float)(long long)(raw >> 18);
                float lo = (float)(int)(raw & 0x3FFFFULL);
                float sum_v = (hi - (float)ENC_OFFSET * (float)cnt)
                            + lo * ENC_INV;
                score += ddp.y + sum_v / (float)cnt + ss;
            }
            float pr = 1.0f / (1.0f + __expf(-score));
            if (twopart) {
                out[n]     = (pr > 0.5f) ? 1.0f : 0.0f;
                out[N + n] = pr;
            } else {
                out[n] = pr;
            }
        }
    }

    // ---- self-reset barrier counters for graph replay ----
    __syncthreads();
    if (tid == 0) {
        __threadfence();
        unsigned old = atomicAdd(&g_done1, 1u);
        if (old == (unsigned)nblk - 1u) {
            g_bar1  = 0u;
            g_done1 = 0u;
            __threadfence();
        }
    }
}

extern "C" void kernel_launch(void* const* d_in, const int* in_sizes, int n_in,
                              void* d_out, int out_size) {
    // metadata order: x_a, edge_index, edge_attr, g_w, g_b, f_w, f_b, cls_w, cls_b
    const float* x_a        = (const float*)d_in[0];
    const void*  edge_index =               d_in[1];
    const float* edge_attr  = (const float*)d_in[2];
    const float* g_w        = (const float*)d_in[3];
    const float* g_b        = (const float*)d_in[4];
    const float* f_w        = (const float*)d_in[5];
    const float* f_b        = (const float*)d_in[6];
    const float* cls_w      = (const float*)d_in[7];
    const float* cls_b      = (const float*)d_in[8];
    float* out = (float*)d_out;

    const int       N = in_sizes[0] / C;        // 20000
    const long long E = (long long)in_sizes[2]; // 640000
    const int twopart = (out_size >= 2 * N) ? 1 : 0;
    const int smem = N * (int)sizeof(float);    // 78.1 KB for N=20000

    static int smem_set = 0;
    if (!smem_set) {
        cudaFuncSetAttribute(main_kernel,
                             cudaFuncAttributeMaxDynamicSharedMemorySize,
                             smem);
        smem_set = 1;
    }

    setup_kernel<<<SU_NBLK, SU_NTHR>>>(g_w, g_b, f_w, f_b, cls_w, cls_b);
    main_kernel<<<MB_NBLK, MB_NTHR, smem>>>(x_a, edge_index, edge_attr, out,
                                            N, E, twopart);
}

// round 10
// speedup vs baseline: 1.1664x; 1.1664x over previous
#include <cuda_runtime.h>
#include <cuda_bf16.h>

// ---------------------------------------------------------------------------
// CutsSelector collapsed to scalar-per-node form:
//   v = f2@cls ; u = f1@cls ; p = Wd@v ; q = Ws@v
//   r = we.v ; s = g_b.v ; c0 = f_b.cls + cls_b
//   t[n]=x[n].q ; du[n]=x[n].u ; dp[n]=x[n].p
//   per edge: acc64[rep][dst] += enc(t[src] + r*ea)  (ONE u64 L2 red, exact
//     fixed point: bits 0..51 value-sum, bits 52..63 count; 4 replicas)
//   score = du + c0 + (cnt>0 ? dp + sum_v/cnt + s : 0) ; probs = sigmoid
//
// FOUR kernels chained with Programmatic Dependent Launch. Each consumer
// front-loads its independent global loads, then cudaGridDependencySynchronize,
// then the dependent computation. Producers trigger right after final stores.
// ---------------------------------------------------------------------------

#define C 128
#define NODE_CAP 24576
#define NREP 4
#define SU_NBLK 32
#define SU_NTHR 256
#define T_NTHR  1024
#define E_NTHR  1024
#define O_NTHR  1024

#define ENC_OFFSET 4096
#define ENC_SCALE  262144.0f          /* 2^18 */
#define ENC_INV    (1.0f / 262144.0f)
#define CNT_SHIFT  52

__device__ __align__(16) float  g_vec_u[C];
__device__ __align__(16) float  g_vec_v[C];
__device__ __align__(16) float  g_vec_p[C];
__device__ __align__(16) float  g_vec_q[C];
__device__ float  g_scalar_r;
__device__ float  g_scalar_s;
__device__ float  g_scalar_c0;
__device__ __align__(16) float  g_t[NODE_CAP];
__device__ __align__(16) float2 g_ddp[NODE_CAP];        // {du, dp}
__device__ __align__(16) unsigned long long g_acc64[NREP * NODE_CAP];
__device__ unsigned g_bar0, g_done0;                    // setup internal barrier

__device__ __forceinline__ float warp_sum(float v) {
    #pragma unroll
    for (int o = 16; o > 0; o >>= 1) v += __shfl_xor_sync(0xffffffffu, v, o);
    return v;
}

// Exact fixed-point edge encoding (validated R5-R9, rel_err 1.25e-7).
__device__ __forceinline__ unsigned long long enc_edge(float v) {
    int   vi  = __float2int_rn(v);
    float fr  = v - (float)vi;                   // exact, |fr| <= 0.5
    int   fri = __float2int_rn(fr * ENC_SCALE);  // exact product (2^18)
    return ((unsigned long long)(unsigned)(vi + ENC_OFFSET) << 18)
         + (unsigned long long)(long long)fri
         + (1ULL << CNT_SHIFT);
}

__device__ __forceinline__ void red_u64(unsigned long long* p,
                                        unsigned long long v) {
    asm volatile("red.global.add.u64 [%0], %1;" :: "l"(p), "l"(v) : "memory");
}

// ============================ K_setup =======================================
__global__ void __launch_bounds__(SU_NTHR, 1)
setup_kernel(const float* __restrict__ g_w,   // [257,128]
             const float* __restrict__ g_b,   // [128]
             const float* __restrict__ f_w,   // [256,128]
             const float* __restrict__ f_b,   // [128]
             const float* __restrict__ cls_w, // [128]
             const float* __restrict__ cls_b) // [1]
{
    const int tid  = threadIdx.x;
    const int bid  = blockIdx.x;
    const int wi   = tid >> 5;
    const int lane = tid & 31;
    const int gwarp = bid * (SU_NTHR / 32) + wi;   // 0..255

    // Stage 1: f_w row `gwarp` dot cls_w -> u (0..127) / v (128..255)
    {
        float4 cc = __ldg((const float4*)cls_w + lane);
        float4 a  = __ldg((const float4*)(f_w + (size_t)gwarp * C) + lane);
        float part = warp_sum(a.x * cc.x + a.y * cc.y + a.z * cc.z + a.w * cc.w);
        if (lane == 0) {
            if (gwarp < C) g_vec_u[gwarp] = part;
            else           g_vec_v[gwarp - C] = part;
        }
    }

    // Zero accumulator replicas while stage-1 latency drains.
    for (int i = bid * SU_NTHR + tid; i < NREP * NODE_CAP; i += SU_NBLK * SU_NTHR)
        g_acc64[i] = 0ULL;

    // internal grid barrier
    __syncthreads();
    if (tid == 0) {
        __threadfence();
        atomicAdd(&g_bar0, 1u);
        unsigned v;
        do {
            asm volatile("ld.global.acquire.gpu.u32 %0, [%1];"
                         : "=r"(v) : "l"(&g_bar0));
        } while (v < (unsigned)gridDim.x);
    }
    __syncthreads();

    // Stage 2: g_w row `gwarp` dot v -> p (0..127) / q (128..255)
    {
        float4 vv = *((const float4*)g_vec_v + lane);
        float4 a  = __ldg((const float4*)(g_w + (size_t)gwarp * C) + lane);
        float part = warp_sum(a.x * vv.x + a.y * vv.y + a.z * vv.z + a.w * vv.w);
        if (lane == 0) {
            if (gwarp < C) g_vec_p[gwarp]     = part;
            else           g_vec_q[gwarp - C] = part;
        }
    }

    // Scalars (block 0, warp 0)
    if (bid == 0 && wi == 0) {
        float r = 0.f, s = 0.f, c = 0.f;
        #pragma unroll
        for (int k = lane; k < C; k += 32) {
            float vk = g_vec_v[k];
            r += __ldg(&g_w[2 * C * C + k]) * vk;
            s += __ldg(&g_b[k]) * vk;
            c += __ldg(&f_b[k]) * __ldg(&cls_w[k]);
        }
        r = warp_sum(r); s = warp_sum(s); c = warp_sum(c);
        if (lane == 0) {
            g_scalar_r  = r;
            g_scalar_s  = s;
            g_scalar_c0 = c + __ldg(&cls_b[0]);
        }
    }

    // Release dependent grid early.
    cudaTriggerProgrammaticLaunchCompletion();

    // Self-reset for graph replay.
    __syncthreads();
    if (tid == 0) {
        __threadfence();
        unsigned old = atomicAdd(&g_done0, 1u);
        if (old == (unsigned)gridDim.x - 1u) {
            g_bar0 = 0u; g_done0 = 0u;
            __threadfence();
        }
    }
}

// ============================ K_t (PDL after setup) =========================
// 4 nodes per warp. Prologue: batched x loads (independent of setup), then
// grid-dependency sync, then dots with q/u/p.
__global__ void __launch_bounds__(T_NTHR, 1)
t_kernel(const float* __restrict__ x, int N)
{
    const int tid  = threadIdx.x;
    const int wi   = tid >> 5;
    const int lane = tid & 31;
    const int gwarp = blockIdx.x * (T_NTHR / 32) + wi;
    const int base  = gwarp * 4;

    float4 xv[4];
    int cnt = 0;
    if (base < N) {
        cnt = (N - base < 4) ? (N - base) : 4;
        #pragma unroll
        for (int j = 0; j < 4; j++)
            if (j < cnt)
                xv[j] = __ldg((const float4*)(x + (size_t)(base + j) * C) + lane);
    }

    cudaGridDependencySynchronize();   // setup results now visible

    if (base >= N) {
        cudaTriggerProgrammaticLaunchCompletion();
        return;
    }

    float4 qv = __ldg((const float4*)g_vec_q + lane);
    float4 uv = __ldg((const float4*)g_vec_u + lane);
    float4 pv = __ldg((const float4*)g_vec_p + lane);

    #pragma unroll
    for (int j = 0; j < 4; j++) {
        if (j < cnt) {
            float dq = xv[j].x * qv.x + xv[j].y * qv.y +
                       xv[j].z * qv.z + xv[j].w * qv.w;
            float du = xv[j].x * uv.x + xv[j].y * uv.y +
                       xv[j].z * uv.z + xv[j].w * uv.w;
            float dp = xv[j].x * pv.x + xv[j].y * pv.y +
                       xv[j].z * pv.z + xv[j].w * pv.w;
            #pragma unroll
            for (int o = 16; o > 0; o >>= 1) {
                dq += __shfl_xor_sync(0xffffffffu, dq, o);
                du += __shfl_xor_sync(0xffffffffu, du, o);
                dp += __shfl_xor_sync(0xffffffffu, dp, o);
            }
            if (lane == 0) {
                g_t[base + j]   = dq;
                g_ddp[base + j] = make_float2(du, dp);
            }
        }
    }

    cudaTriggerProgrammaticLaunchCompletion();
}

// ============================ K_edge (PDL after t) ==========================
// 1 quad (4 edges) per thread. Prologue: load edge indices/attrs (independent
// of t), sync, then gather t + one u64 red per edge.
__global__ void __launch_bounds__(E_NTHR, 1)
edge_kernel(const void*  __restrict__ eidx,
            const float* __restrict__ ea,
            long long E)
{
    const int tid  = threadIdx.x;
    const long long gtid = (long long)blockIdx.x * E_NTHR + tid;
    const long long quads = E >> 2;

    // per-warp dtype sniff (no cross-warp dependency)
    const int lane = tid & 31;
    int is64;
    {
        const int* p = (const int*)eidx;
        int ok = (p[2 * lane + 1] == 0) &&
                 (p[2 * (lane + 32) + 1] == 0) &&
                 (p[2 * (lane + 64) + 1] == 0);
        unsigned b = __ballot_sync(0xffffffffu, ok);
        is64 = (b == 0xffffffffu) ? 1 : 0;
    }

    // Prologue loads (independent of t_kernel)
    long long s0 = 0, s1 = 0, s2 = 0, s3 = 0;
    long long d0 = 0, d1 = 0, d2 = 0, d3 = 0;
    float4 e4 = make_float4(0.f, 0.f, 0.f, 0.f);
    const bool active = (gtid < quads);
    if (active) {
        e4 = __ldg((const float4*)ea + gtid);
        if (is64) {
            const longlong2* ps = (const longlong2*)eidx;
            const longlong2* pd = (const longlong2*)((const long long*)eidx + E);
            longlong2 a = ps[2 * gtid], b = ps[2 * gtid + 1];
            longlong2 c = pd[2 * gtid], d = pd[2 * gtid + 1];
            s0 = a.x; s1 = a.y; s2 = b.x; s3 = b.y;
            d0 = c.x; d1 = c.y; d2 = d.x; d3 = d.y;
        } else {
            const int4* ps = (const int4*)eidx;
            const int4* pd = (const int4*)((const int*)eidx + E);
            int4 a = ps[gtid], c = pd[gtid];
            s0 = a.x; s1 = a.y; s2 = a.z; s3 = a.w;
            d0 = c.x; d1 = c.y; d2 = c.z; d3 = c.w;
        }
    }

    cudaGridDependencySynchronize();   // g_t / g_scalar_r now visible

    const float rs = g_scalar_r;
    unsigned long long* acc =
        g_acc64 + (size_t)(blockIdx.x & (NREP - 1)) * NODE_CAP;

    if (active) {
        float v0 = __ldg(&g_t[s0]) + e4.x * rs;
        float v1 = __ldg(&g_t[s1]) + e4.y * rs;
        float v2 = __ldg(&g_t[s2]) + e4.z * rs;
        float v3 = __ldg(&g_t[s3]) + e4.w * rs;
        red_u64(&acc[d0], enc_edge(v0));
        red_u64(&acc[d1], enc_edge(v1));
        red_u64(&acc[d2], enc_edge(v2));
        red_u64(&acc[d3], enc_edge(v3));
    }
    if (gtid == 0) {
        if (is64) {
            const long long* p = (const long long*)eidx;
            for (long long e = quads << 2; e < E; e++) {
                float v = __ldg(&g_t[p[e]]) + ea[e] * rs;
                red_u64(&acc[p[E + e]], enc_edge(v));
            }
        } else {
            const int* p = (const int*)eidx;
            for (long long e = quads << 2; e < E; e++) {
                float v = __ldg(&g_t[p[e]]) + ea[e] * rs;
                red_u64(&acc[p[E + e]], enc_edge(v));
            }
        }
    }
    // No early trigger here: the out kernel must see ALL reds, and reds have
    // no completion signal other than kernel end. Implicit trigger at exit.
}

// ============================ K_out (PDL after edge) ========================
__global__ void __launch_bounds__(O_NTHR, 1)
out_kernel(float* __restrict__ out, int N, int twopart)
{
    const int n = blockIdx.x * O_NTHR + threadIdx.x;

    // Prologue: ddp is ready (produced two kernels back).
    float2 ddp = make_float2(0.f, 0.f);
    if (n < N) ddp = g_ddp[n];

    cudaGridDependencySynchronize();   // all edge reds complete

    if (n >= N) return;

    unsigned long long acc = g_acc64[n]
                           + g_acc64[NODE_CAP + n]
                           + g_acc64[2 * NODE_CAP + n]
                           + g_acc64[3 * NODE_CAP + n];
    unsigned cnt = (unsigned)(acc >> CNT_SHIFT);
    unsigned long long raw = acc & ((1ULL << CNT_SHIFT) - 1ULL);
    float score = ddp.x + g_scalar_c0;
    if (cnt > 0u) {
        // hi, lo and 4096*cnt are exact integers < 2^24 in fp32.
        float hi = (float)(long long)(raw >> 18);
        float lo = (float)(int)(raw & 0x3FFFFULL);
        float sum_v = (hi - (float)ENC_OFFSET * (float)cnt) + lo * ENC_INV;
        score += ddp.y + sum_v / (float)cnt + g_scalar_s;
    }
    float pr = 1.0f / (1.0f + __expf(-score));
    if (twopart) {
        out[n]     = (pr > 0.5f) ? 1.0f : 0.0f;
        out[N + n] = pr;
    } else {
        out[n] = pr;
    }
}

// ============================ host ==========================================
static void launch_pdl(const void* func, dim3 grid, dim3 block, void** args) {
    cudaLaunchConfig_t cfg = {};
    cfg.gridDim  = grid;
    cfg.blockDim = block;
    cfg.dynamicSmemBytes = 0;
    cfg.stream = 0;
    cudaLaunchAttribute attr[1];
    attr[0].id = cudaLaunchAttributeProgrammaticStreamSerialization;
    attr[0].val.programmaticStreamSerializationAllowed = 1;
    cfg.attrs = attr;
    cfg.numAttrs = 1;
    cudaLaunchKernelExC(&cfg, func, args);
}

extern "C" void kernel_launch(void* const* d_in, const int* in_sizes, int n_in,
                              void* d_out, int out_size) {
    // metadata order: x_a, edge_index, edge_attr, g_w, g_b, f_w, f_b, cls_w, cls_b
    const float* x_a        = (const float*)d_in[0];
    const void*  edge_index =               d_in[1];
    const float* edge_attr  = (const float*)d_in[2];
    const float* g_w        = (const float*)d_in[3];
    const float* g_b        = (const float*)d_in[4];
    const float* f_w        = (const float*)d_in[5];
    const float* f_b        = (const float*)d_in[6];
    const float* cls_w      = (const float*)d_in[7];
    const float* cls_b      = (const float*)d_in[8];
    float* out = (float*)d_out;

    int       N = in_sizes[0] / C;        // 20000
    long long E = (long long)in_sizes[2]; // 640000
    int twopart = (out_size >= 2 * N) ? 1 : 0;

    setup_kernel<<<SU_NBLK, SU_NTHR>>>(g_w, g_b, f_w, f_b, cls_w, cls_b);

    {   // t kernel: 4 nodes/warp
        int warps = (N + 3) / 4;
        dim3 grid((warps + T_NTHR / 32 - 1) / (T_NTHR / 32));
        void* args[] = {(void*)&x_a, (void*)&N};
        launch_pdl((const void*)t_kernel, grid, dim3(T_NTHR), args);
    }
    {   // edge kernel: 1 quad/thread
        long long quads = E >> 2;
        dim3 grid((unsigned)((quads + E_NTHR - 1) / E_NTHR));
        void* args[] = {(void*)&edge_index, (void*)&edge_attr, (void*)&E};
        launch_pdl((const void*)edge_kernel, grid, dim3(E_NTHR), args);
    }
    {   // out kernel
        dim3 grid((N + O_NTHR - 1) / O_NTHR);
        void* args[] = {(void*)&out, (void*)&N, (void*)&twopart};
        launch_pdl((const void*)out_kernel, grid, dim3(O_NTHR), args);
    }
}

// round 11
// speedup vs baseline: 1.1778x; 1.0097x over previous
#include <cuda_runtime.h>
#include <cuda_bf16.h>

// ---------------------------------------------------------------------------
// CutsSelector collapsed to scalar-per-node form:
//   v = f2@cls ; u = f1@cls ; p = Wd@v ; q = Ws@v
//   r = we.v ; s = g_b.v ; c0 = f_b.cls + cls_b
//   t[n]=x[n].q ; du[n]=x[n].u ; dp[n]=x[n].p
//   per edge: acc64[rep][dst] += enc(t[src] + r*ea)  (ONE u64 L2 red, exact
//     fixed point: bits 0..51 value-sum, bits 52..63 count; 4 replicas)
//   score = du + c0 + (cnt>0 ? dp + sum_v/cnt + s : 0) ; probs = sigmoid
//
// FOUR kernels chained with Programmatic Dependent Launch (validated R10:
// 25.1 -> 23.3us). Each consumer front-loads its independent global loads,
// then cudaGridDependencySynchronize, then the dependent computation.
// R11: edge kernel 2 edges/thread (2x threads, latency-bound section).
// ---------------------------------------------------------------------------

#define C 128
#define NODE_CAP 24576
#define NREP 4
#define SU_NBLK 32
#define SU_NTHR 256
#define T_NTHR  1024
#define E_NTHR  1024
#define O_NTHR  256

#define ENC_OFFSET 4096
#define ENC_SCALE  262144.0f          /* 2^18 */
#define ENC_INV    (1.0f / 262144.0f)
#define CNT_SHIFT  52

__device__ __align__(16) float  g_vec_u[C];
__device__ __align__(16) float  g_vec_v[C];
__device__ __align__(16) float  g_vec_p[C];
__device__ __align__(16) float  g_vec_q[C];
__device__ float  g_scalar_r;
__device__ float  g_scalar_s;
__device__ float  g_scalar_c0;
__device__ __align__(16) float  g_t[NODE_CAP];
__device__ __align__(16) float2 g_ddp[NODE_CAP];        // {du, dp}
__device__ __align__(16) unsigned long long g_acc64[NREP * NODE_CAP];
__device__ unsigned g_bar0, g_done0;                    // setup internal barrier

__device__ __forceinline__ float warp_sum(float v) {
    #pragma unroll
    for (int o = 16; o > 0; o >>= 1) v += __shfl_xor_sync(0xffffffffu, v, o);
    return v;
}

// Exact fixed-point edge encoding (validated R5-R10, rel_err 1.25e-7).
__device__ __forceinline__ unsigned long long enc_edge(float v) {
    int   vi  = __float2int_rn(v);
    float fr  = v - (float)vi;                   // exact, |fr| <= 0.5
    int   fri = __float2int_rn(fr * ENC_SCALE);  // exact product (2^18)
    return ((unsigned long long)(unsigned)(vi + ENC_OFFSET) << 18)
         + (unsigned long long)(long long)fri
         + (1ULL << CNT_SHIFT);
}

__device__ __forceinline__ void red_u64(unsigned long long* p,
                                        unsigned long long v) {
    asm volatile("red.global.add.u64 [%0], %1;" :: "l"(p), "l"(v) : "memory");
}

// ============================ K_setup =======================================
__global__ void __launch_bounds__(SU_NTHR, 1)
setup_kernel(const float* __restrict__ g_w,   // [257,128]
             const float* __restrict__ g_b,   // [128]
             const float* __restrict__ f_w,   // [256,128]
             const float* __restrict__ f_b,   // [128]
             const float* __restrict__ cls_w, // [128]
             const float* __restrict__ cls_b) // [1]
{
    const int tid  = threadIdx.x;
    const int bid  = blockIdx.x;
    const int wi   = tid >> 5;
    const int lane = tid & 31;
    const int gwarp = bid * (SU_NTHR / 32) + wi;   // 0..255

    // Stage 1: f_w row `gwarp` dot cls_w -> u (0..127) / v (128..255)
    {
        float4 cc = __ldg((const float4*)cls_w + lane);
        float4 a  = __ldg((const float4*)(f_w + (size_t)gwarp * C) + lane);
        float part = warp_sum(a.x * cc.x + a.y * cc.y + a.z * cc.z + a.w * cc.w);
        if (lane == 0) {
            if (gwarp < C) g_vec_u[gwarp] = part;
            else           g_vec_v[gwarp - C] = part;
        }
    }

    // Zero accumulator replicas while stage-1 latency drains.
    for (int i = bid * SU_NTHR + tid; i < NREP * NODE_CAP; i += SU_NBLK * SU_NTHR)
        g_acc64[i] = 0ULL;

    // internal grid barrier
    __syncthreads();
    if (tid == 0) {
        __threadfence();
        atomicAdd(&g_bar0, 1u);
        unsigned v;
        do {
            asm volatile("ld.global.acquire.gpu.u32 %0, [%1];"
                         : "=r"(v) : "l"(&g_bar0));
        } while (v < (unsigned)gridDim.x);
    }
    __syncthreads();

    // Stage 2: g_w row `gwarp` dot v -> p (0..127) / q (128..255)
    {
        float4 vv = *((const float4*)g_vec_v + lane);
        float4 a  = __ldg((const float4*)(g_w + (size_t)gwarp * C) + lane);
        float part = warp_sum(a.x * vv.x + a.y * vv.y + a.z * vv.z + a.w * vv.w);
        if (lane == 0) {
            if (gwarp < C) g_vec_p[gwarp]     = part;
            else           g_vec_q[gwarp - C] = part;
        }
    }

    // Scalars (block 0, warp 0)
    if (bid == 0 && wi == 0) {
        float r = 0.f, s = 0.f, c = 0.f;
        #pragma unroll
        for (int k = lane; k < C; k += 32) {
            float vk = g_vec_v[k];
            r += __ldg(&g_w[2 * C * C + k]) * vk;
            s += __ldg(&g_b[k]) * vk;
            c += __ldg(&f_b[k]) * __ldg(&cls_w[k]);
        }
        r = warp_sum(r); s = warp_sum(s); c = warp_sum(c);
        if (lane == 0) {
            g_scalar_r  = r;
            g_scalar_s  = s;
            g_scalar_c0 = c + __ldg(&cls_b[0]);
        }
    }

    // Release dependent grid early.
    cudaTriggerProgrammaticLaunchCompletion();

    // Self-reset for graph replay.
    __syncthreads();
    if (tid == 0) {
        __threadfence();
        unsigned old = atomicAdd(&g_done0, 1u);
        if (old == (unsigned)gridDim.x - 1u) {
            g_bar0 = 0u; g_done0 = 0u;
            __threadfence();
        }
    }
}

// ============================ K_t (PDL after setup) =========================
// 4 nodes per warp. Prologue: batched x loads (independent of setup), then
// grid-dependency sync, then dots with q/u/p.
__global__ void __launch_bounds__(T_NTHR, 1)
t_kernel(const float* __restrict__ x, int N)
{
    const int tid  = threadIdx.x;
    const int wi   = tid >> 5;
    const int lane = tid & 31;
    const int gwarp = blockIdx.x * (T_NTHR / 32) + wi;
    const int base  = gwarp * 4;

    float4 xv[4];
    int cnt = 0;
    if (base < N) {
        cnt = (N - base < 4) ? (N - base) : 4;
        #pragma unroll
        for (int j = 0; j < 4; j++)
            if (j < cnt)
                xv[j] = __ldg((const float4*)(x + (size_t)(base + j) * C) + lane);
    }

    cudaGridDependencySynchronize();   // setup results now visible

    if (base >= N) {
        cudaTriggerProgrammaticLaunchCompletion();
        return;
    }

    float4 qv = __ldg((const float4*)g_vec_q + lane);
    float4 uv = __ldg((const float4*)g_vec_u + lane);
    float4 pv = __ldg((const float4*)g_vec_p + lane);

    #pragma unroll
    for (int j = 0; j < 4; j++) {
        if (j < cnt) {
            float dq = xv[j].x * qv.x + xv[j].y * qv.y +
                       xv[j].z * qv.z + xv[j].w * qv.w;
            float du = xv[j].x * uv.x + xv[j].y * uv.y +
                       xv[j].z * uv.z + xv[j].w * uv.w;
            float dp = xv[j].x * pv.x + xv[j].y * pv.y +
                       xv[j].z * pv.z + xv[j].w * pv.w;
            #pragma unroll
            for (int o = 16; o > 0; o >>= 1) {
                dq += __shfl_xor_sync(0xffffffffu, dq, o);
                du += __shfl_xor_sync(0xffffffffu, du, o);
                dp += __shfl_xor_sync(0xffffffffu, dp, o);
            }
            if (lane == 0) {
                g_t[base + j]   = dq;
                g_ddp[base + j] = make_float2(du, dp);
            }
        }
    }

    cudaTriggerProgrammaticLaunchCompletion();
}

// ============================ K_edge (PDL after t) ==========================
// 2 edges per thread (R11: double the resident threads in the latency-bound
// gather+red section). Prologue: load edge indices/attrs, sync, then gather
// t + one u64 red per edge.
__global__ void __launch_bounds__(E_NTHR, 1)
edge_kernel(const void*  __restrict__ eidx,
            const float* __restrict__ ea,
            long long E)
{
    const int tid  = threadIdx.x;
    const long long gtid  = (long long)blockIdx.x * E_NTHR + tid;
    const long long pairs = E >> 1;

    // per-warp dtype sniff (no cross-warp dependency)
    const int lane = tid & 31;
    int is64;
    {
        const int* p = (const int*)eidx;
        int ok = (p[2 * lane + 1] == 0) &&
                 (p[2 * (lane + 32) + 1] == 0) &&
                 (p[2 * (lane + 64) + 1] == 0);
        unsigned b = __ballot_sync(0xffffffffu, ok);
        is64 = (b == 0xffffffffu) ? 1 : 0;
    }

    // Prologue loads (independent of t_kernel)
    long long s0 = 0, s1 = 0, d0 = 0, d1 = 0;
    float2 e2 = make_float2(0.f, 0.f);
    const bool active = (gtid < pairs);
    if (active) {
        e2 = __ldg((const float2*)ea + gtid);
        if (is64) {
            const longlong2* ps = (const longlong2*)eidx;
            const longlong2* pd = (const longlong2*)((const long long*)eidx + E);
            longlong2 a = ps[gtid];
            longlong2 c = pd[gtid];
            s0 = a.x; s1 = a.y;
            d0 = c.x; d1 = c.y;
        } else {
            const int2* ps = (const int2*)eidx;
            const int2* pd = (const int2*)((const int*)eidx + E);
            int2 a = ps[gtid];
            int2 c = pd[gtid];
            s0 = a.x; s1 = a.y;
            d0 = c.x; d1 = c.y;
        }
    }

    cudaGridDependencySynchronize();   // g_t / g_scalar_r now visible

    const float rs = g_scalar_r;
    unsigned long long* acc =
        g_acc64 + (size_t)(blockIdx.x & (NREP - 1)) * NODE_CAP;

    if (active) {
        float v0 = __ldg(&g_t[s0]) + e2.x * rs;
        float v1 = __ldg(&g_t[s1]) + e2.y * rs;
        red_u64(&acc[d0], enc_edge(v0));
        red_u64(&acc[d1], enc_edge(v1));
    }
    if (gtid == 0 && (E & 1)) {
        if (is64) {
            const long long* p = (const long long*)eidx;
            float v = __ldg(&g_t[p[E - 1]]) + ea[E - 1] * rs;
            red_u64(&acc[p[2 * E - 1]], enc_edge(v));
        } else {
            const int* p = (const int*)eidx;
            float v = __ldg(&g_t[p[E - 1]]) + ea[E - 1] * rs;
            red_u64(&acc[p[2 * E - 1]], enc_edge(v));
        }
    }
    // Implicit PDL trigger at exit: out kernel must see ALL reds.
}

// ============================ K_out (PDL after edge) ========================
__global__ void __launch_bounds__(O_NTHR, 8)
out_kernel(float* __restrict__ out, int N, int twopart)
{
    const int n = blockIdx.x * O_NTHR + threadIdx.x;

    // Prologue: ddp is ready (produced two kernels back).
    float2 ddp = make_float2(0.f, 0.f);
    if (n < N) ddp = g_ddp[n];

    cudaGridDependencySynchronize();   // all edge reds complete

    if (n >= N) return;

    unsigned long long acc = g_acc64[n]
                           + g_acc64[NODE_CAP + n]
                           + g_acc64[2 * NODE_CAP + n]
                           + g_acc64[3 * NODE_CAP + n];
    unsigned cnt = (unsigned)(acc >> CNT_SHIFT);
    unsigned long long raw = acc & ((1ULL << CNT_SHIFT) - 1ULL);
    float score = ddp.x + g_scalar_c0;
    if (cnt > 0u) {
        // hi, lo and 4096*cnt are exact integers < 2^24 in fp32.
        float hi = (float)(long long)(raw >> 18);
        float lo = (float)(int)(raw & 0x3FFFFULL);
        float sum_v = (hi - (float)ENC_OFFSET * (float)cnt) + lo * ENC_INV;
        score += ddp.y + sum_v / (float)cnt + g_scalar_s;
    }
    float pr = 1.0f / (1.0f + __expf(-score));
    if (twopart) {
        out[n]     = (pr > 0.5f) ? 1.0f : 0.0f;
        out[N + n] = pr;
    } else {
        out[n] = pr;
    }
}

// ============================ host ==========================================
static void launch_pdl(const void* func, dim3 grid, dim3 block, void** args) {
    cudaLaunchConfig_t cfg = {};
    cfg.gridDim  = grid;
    cfg.blockDim = block;
    cfg.dynamicSmemBytes = 0;
    cfg.stream = 0;
    cudaLaunchAttribute attr[1];
    attr[0].id = cudaLaunchAttributeProgrammaticStreamSerialization;
    attr[0].val.programmaticStreamSerializationAllowed = 1;
    cfg.attrs = attr;
    cfg.numAttrs = 1;
    cudaLaunchKernelExC(&cfg, func, args);
}

extern "C" void kernel_launch(void* const* d_in, const int* in_sizes, int n_in,
                              void* d_out, int out_size) {
    // metadata order: x_a, edge_index, edge_attr, g_w, g_b, f_w, f_b, cls_w, cls_b
    const float* x_a        = (const float*)d_in[0];
    const void*  edge_index =               d_in[1];
    const float* edge_attr  = (const float*)d_in[2];
    const float* g_w        = (const float*)d_in[3];
    const float* g_b        = (const float*)d_in[4];
    const float* f_w        = (const float*)d_in[5];
    const float* f_b        = (const float*)d_in[6];
    const float* cls_w      = (const float*)d_in[7];
    const float* cls_b      = (const float*)d_in[8];
    float* out = (float*)d_out;

    int       N = in_sizes[0] / C;        // 20000
    long long E = (long long)in_sizes[2]; // 640000
    int twopart = (out_size >= 2 * N) ? 1 : 0;

    setup_kernel<<<SU_NBLK, SU_NTHR>>>(g_w, g_b, f_w, f_b, cls_w, cls_b);

    {   // t kernel: 4 nodes/warp
        int warps = (N + 3) / 4;
        dim3 grid((warps + T_NTHR / 32 - 1) / (T_NTHR / 32));
        void* args[] = {(void*)&x_a, (void*)&N};
        launch_pdl((const void*)t_kernel, grid, dim3(T_NTHR), args);
    }
    {   // edge kernel: 2 edges/thread
        long long pairs = E >> 1;
        dim3 grid((unsigned)((pairs + E_NTHR - 1) / E_NTHR));
        void* args[] = {(void*)&edge_index, (void*)&edge_attr, (void*)&E};
        launch_pdl((const void*)edge_kernel, grid, dim3(E_NTHR), args);
    }
    {   // out kernel
        dim3 grid((N + O_NTHR - 1) / O_NTHR);
        void* args[] = {(void*)&out, (void*)&N, (void*)&twopart};
        launch_pdl((const void*)out_kernel, grid, dim3(O_NTHR), args);
    }
}

// round 12
// speedup vs baseline: 1.2771x; 1.0843x over previous
#include <cuda_runtime.h>
#include <cuda_bf16.h>

// ---------------------------------------------------------------------------
// CutsSelector collapsed to scalar-per-node form:
//   v = f2@cls ; u = f1@cls ; p = Wd@v ; q = Ws@v
//   r = we.v ; s = g_b.v ; c0 = f_b.cls + cls_b
//   t[n]=x[n].q ; du[n]=x[n].u ; dp[n]=x[n].p
//   per edge: acc64[rep][dst] += enc(t[src] + r*ea)  (ONE u64 L2 red, exact
//     fixed point: bits 0..51 value-sum, bits 52..63 count; 4 replicas)
//   score = du + c0 + (cnt>0 ? dp + sum_v/cnt + s : 0) ; probs = sigmoid
//
// THREE kernels, PDL-chained (R10/R11 validated: 25.1 -> 23.0us):
//   K1 pre_kernel (148 x 1024, 2 internal grid barriers): prologue issues the
//      10MB x read into registers, overlapping the two matvec stages; dots
//      consume the x registers after barrier 2. Zeroes acc replicas.
//   K2 edge_kernel (PDL): prologue loads edge data during K1; gather+red.
//   K3 out_kernel  (PDL): decode + sigmoid.
// ---------------------------------------------------------------------------

#define C 128
#define NODE_CAP 24576
#define NREP 4
#define P_NBLK 148
#define P_NTHR 1024
#define NPW    5            /* nodes per warp in K1: 148*32*5 = 23680 >= N */
#define E_NTHR 1024
#define O_NTHR 256

#define ENC_OFFSET 4096
#define ENC_SCALE  262144.0f          /* 2^18 */
#define ENC_INV    (1.0f / 262144.0f)
#define CNT_SHIFT  52

__device__ __align__(16) float  g_vec_u[C];
__device__ __align__(16) float  g_vec_v[C];
__device__ __align__(16) float  g_vec_p[C];
__device__ __align__(16) float  g_vec_q[C];
__device__ float  g_scalar_r;
__device__ float  g_scalar_s;
__device__ float  g_scalar_c0;
__device__ __align__(16) float  g_t[NODE_CAP];
__device__ __align__(16) float2 g_ddp[NODE_CAP];        // {du, dp}
__device__ __align__(16) unsigned long long g_acc64[NREP * NODE_CAP];
__device__ unsigned g_bar0, g_done0;                    // K1 barriers

__device__ __forceinline__ float warp_sum(float v) {
    #pragma unroll
    for (int o = 16; o > 0; o >>= 1) v += __shfl_xor_sync(0xffffffffu, v, o);
    return v;
}

// Exact fixed-point edge encoding (validated R5-R11, rel_err 1.25e-7).
__device__ __forceinline__ unsigned long long enc_edge(float v) {
    int   vi  = __float2int_rn(v);
    float fr  = v - (float)vi;                   // exact, |fr| <= 0.5
    int   fri = __float2int_rn(fr * ENC_SCALE);  // exact product (2^18)
    return ((unsigned long long)(unsigned)(vi + ENC_OFFSET) << 18)
         + (unsigned long long)(long long)fri
         + (1ULL << CNT_SHIFT);
}

__device__ __forceinline__ void red_u64(unsigned long long* p,
                                        unsigned long long v) {
    asm volatile("red.global.add.u64 [%0], %1;" :: "l"(p), "l"(v) : "memory");
}

__device__ __forceinline__ void spin_barrier(unsigned* bar, unsigned target) {
    __syncthreads();
    if (threadIdx.x == 0) {
        __threadfence();
        atomicAdd(bar, 1u);
        unsigned v;
        do {
            asm volatile("ld.global.acquire.gpu.u32 %0, [%1];"
                         : "=r"(v) : "l"(bar));
        } while (v < target);
    }
    __syncthreads();
}

// ============================ K1: setup + t =================================
__global__ void __launch_bounds__(P_NTHR, 1)
pre_kernel(const float* __restrict__ x,
           const float* __restrict__ g_w,   // [257,128]
           const float* __restrict__ g_b,   // [128]
           const float* __restrict__ f_w,   // [256,128]
           const float* __restrict__ f_b,   // [128]
           const float* __restrict__ cls_w, // [128]
           const float* __restrict__ cls_b, // [1]
           int N)
{
    const int tid  = threadIdx.x;
    const int bid  = blockIdx.x;
    const int wi   = tid >> 5;
    const int lane = tid & 31;
    const int gwarp = bid * (P_NTHR / 32) + wi;    // 0..4735

    // ---- setup stage 1 first on the 8 blocks that own matvec rows ----
    // (issue the dependent f_w loads before the bulk x loads on those SMs)
    if (gwarp < 2 * C) {
        float4 cc = __ldg((const float4*)cls_w + lane);
        float4 a  = __ldg((const float4*)(f_w + (size_t)gwarp * C) + lane);
        float part = warp_sum(a.x * cc.x + a.y * cc.y + a.z * cc.z + a.w * cc.w);
        if (lane == 0) {
            if (gwarp < C) g_vec_u[gwarp] = part;
            else           g_vec_v[gwarp - C] = part;
        }
    }

    // ---- prologue: issue this warp's x rows (consumed only after bar 2) ----
    const int base = gwarp * NPW;
    const int cnt  = (base < N) ? ((N - base < NPW) ? (N - base) : NPW) : 0;
    float4 xv[NPW];
    #pragma unroll
    for (int j = 0; j < NPW; j++)
        if (j < cnt)
            xv[j] = __ldg((const float4*)(x + (size_t)(base + j) * C) + lane);

    // ---- zero accumulator replicas ----
    {
        int i = bid * P_NTHR + tid;               // grid covers 151552 > 98304
        if (i < NREP * NODE_CAP) g_acc64[i] = 0ULL;
    }

    spin_barrier(&g_bar0, (unsigned)P_NBLK);

    // ---- setup stage 2 ----
    if (gwarp < 2 * C) {
        float4 vv = *((const float4*)g_vec_v + lane);
        float4 a  = __ldg((const float4*)(g_w + (size_t)gwarp * C) + lane);
        float part = warp_sum(a.x * vv.x + a.y * vv.y + a.z * vv.z + a.w * vv.w);
        if (lane == 0) {
            if (gwarp < C) g_vec_p[gwarp]     = part;
            else           g_vec_q[gwarp - C] = part;
        }
    }
    // scalars on a block not doing stage 2
    if (bid == 8 && wi == 0) {
        float r = 0.f, s = 0.f, c = 0.f;
        #pragma unroll
        for (int k = lane; k < C; k += 32) {
            float vk = g_vec_v[k];
            r += __ldg(&g_w[2 * C * C + k]) * vk;
            s += __ldg(&g_b[k]) * vk;
            c += __ldg(&f_b[k]) * __ldg(&cls_w[k]);
        }
        r = warp_sum(r); s = warp_sum(s); c = warp_sum(c);
        if (lane == 0) {
            g_scalar_r  = r;
            g_scalar_s  = s;
            g_scalar_c0 = c + __ldg(&cls_b[0]);
        }
    }

    spin_barrier(&g_bar0, 2u * (unsigned)P_NBLK);

    // ---- dots: x registers are in flight/arrived; q/u/p are L2-hot ----
    if (cnt > 0) {
        float4 qv = *((const float4*)g_vec_q + lane);
        float4 uv = *((const float4*)g_vec_u + lane);
        float4 pv = *((const float4*)g_vec_p + lane);
        #pragma unroll
        for (int j = 0; j < NPW; j++) {
            if (j < cnt) {
                float dq = xv[j].x * qv.x + xv[j].y * qv.y +
                           xv[j].z * qv.z + xv[j].w * qv.w;
                float du = xv[j].x * uv.x + xv[j].y * uv.y +
                           xv[j].z * uv.z + xv[j].w * uv.w;
                float dp = xv[j].x * pv.x + xv[j].y * pv.y +
                           xv[j].z * pv.z + xv[j].w * pv.w;
                #pragma unroll
                for (int o = 16; o > 0; o >>= 1) {
                    dq += __shfl_xor_sync(0xffffffffu, dq, o);
                    du += __shfl_xor_sync(0xffffffffu, du, o);
                    dp += __shfl_xor_sync(0xffffffffu, dp, o);
                }
                if (lane == 0) {
                    g_t[base + j]   = dq;
                    g_ddp[base + j] = make_float2(du, dp);
                }
            }
        }
    }

    cudaTriggerProgrammaticLaunchCompletion();

    // ---- self-reset barrier counters for graph replay ----
    __syncthreads();
    if (tid == 0) {
        __threadfence();
        unsigned old = atomicAdd(&g_done0, 1u);
        if (old == (unsigned)P_NBLK - 1u) {
            g_bar0 = 0u; g_done0 = 0u;
            __threadfence();
        }
    }
}

// ============================ K2: edges (PDL) ===============================
// 2 edges per thread. Prologue: load edge indices/attrs (independent of K1,
// overlaps K1's full runtime), sync, then gather t + one u64 red per edge.
__global__ void __launch_bounds__(E_NTHR, 1)
edge_kernel(const void*  __restrict__ eidx,
            const float* __restrict__ ea,
            long long E)
{
    const int tid  = threadIdx.x;
    const long long gtid  = (long long)blockIdx.x * E_NTHR + tid;
    const long long pairs = E >> 1;

    // per-warp dtype sniff: int64 nonneg < 2^31 shows zeros at odd int32 slots
    const int lane = tid & 31;
    int is64;
    {
        const int* p = (const int*)eidx;
        int ok = (p[2 * lane + 1] == 0) &&
                 (p[2 * (lane + 32) + 1] == 0) &&
                 (p[2 * (lane + 64) + 1] == 0);
        unsigned b = __ballot_sync(0xffffffffu, ok);
        is64 = (b == 0xffffffffu) ? 1 : 0;
    }

    long long s0 = 0, s1 = 0, d0 = 0, d1 = 0;
    float2 e2 = make_float2(0.f, 0.f);
    const bool active = (gtid < pairs);
    if (active) {
        e2 = __ldg((const float2*)ea + gtid);
        if (is64) {
            const longlong2* ps = (const longlong2*)eidx;
            const longlong2* pd = (const longlong2*)((const long long*)eidx + E);
            longlong2 a = ps[gtid];
            longlong2 c = pd[gtid];
            s0 = a.x; s1 = a.y; d0 = c.x; d1 = c.y;
        } else {
            const int2* ps = (const int2*)eidx;
            const int2* pd = (const int2*)((const int*)eidx + E);
            int2 a = ps[gtid];
            int2 c = pd[gtid];
            s0 = a.x; s1 = a.y; d0 = c.x; d1 = c.y;
        }
    }

    cudaGridDependencySynchronize();   // g_t / g_scalar_r / zeroed acc visible

    const float rs = g_scalar_r;
    unsigned long long* acc =
        g_acc64 + (size_t)(blockIdx.x & (NREP - 1)) * NODE_CAP;

    if (active) {
        float v0 = __ldg(&g_t[s0]) + e2.x * rs;
        float v1 = __ldg(&g_t[s1]) + e2.y * rs;
        red_u64(&acc[d0], enc_edge(v0));
        red_u64(&acc[d1], enc_edge(v1));
    }
    if (gtid == 0 && (E & 1)) {
        if (is64) {
            const long long* p = (const long long*)eidx;
            float v = __ldg(&g_t[p[E - 1]]) + ea[E - 1] * rs;
            red_u64(&acc[p[2 * E - 1]], enc_edge(v));
        } else {
            const int* p = (const int*)eidx;
            float v = __ldg(&g_t[p[E - 1]]) + ea[E - 1] * rs;
            red_u64(&acc[p[2 * E - 1]], enc_edge(v));
        }
    }
    // Implicit PDL trigger at exit: out kernel must see ALL reds.
}

// ============================ K3: output (PDL) ==============================
__global__ void __launch_bounds__(O_NTHR, 8)
out_kernel(float* __restrict__ out, int N, int twopart)
{
    const int n = blockIdx.x * O_NTHR + threadIdx.x;

    float2 ddp = make_float2(0.f, 0.f);
    if (n < N) ddp = g_ddp[n];

    cudaGridDependencySynchronize();   // all edge reds complete

    if (n >= N) return;

    unsigned long long acc = g_acc64[n]
                           + g_acc64[NODE_CAP + n]
                           + g_acc64[2 * NODE_CAP + n]
                           + g_acc64[3 * NODE_CAP + n];
    unsigned cnt = (unsigned)(acc >> CNT_SHIFT);
    unsigned long long raw = acc & ((1ULL << CNT_SHIFT) - 1ULL);
    float score = ddp.x + g_scalar_c0;
    if (cnt > 0u) {
        // hi, lo and 4096*cnt are exact integers < 2^24 in fp32.
        float hi = (float)(long long)(raw >> 18);
        float lo = (float)(int)(raw & 0x3FFFFULL);
        float sum_v = (hi - (float)ENC_OFFSET * (float)cnt) + lo * ENC_INV;
        score += ddp.y + sum_v / (float)cnt + g_scalar_s;
    }
    float pr = 1.0f / (1.0f + __expf(-score));
    if (twopart) {
        out[n]     = (pr > 0.5f) ? 1.0f : 0.0f;
        out[N + n] = pr;
    } else {
        out[n] = pr;
    }
}

// ============================ host ==========================================
static void launch_pdl(const void* func, dim3 grid, dim3 block, void** args) {
    cudaLaunchConfig_t cfg = {};
    cfg.gridDim  = grid;
    cfg.blockDim = block;
    cfg.dynamicSmemBytes = 0;
    cfg.stream = 0;
    cudaLaunchAttribute attr[1];
    attr[0].id = cudaLaunchAttributeProgrammaticStreamSerialization;
    attr[0].val.programmaticStreamSerializationAllowed = 1;
    cfg.attrs = attr;
    cfg.numAttrs = 1;
    cudaLaunchKernelExC(&cfg, func, args);
}

extern "C" void kernel_launch(void* const* d_in, const int* in_sizes, int n_in,
                              void* d_out, int out_size) {
    // metadata order: x_a, edge_index, edge_attr, g_w, g_b, f_w, f_b, cls_w, cls_b
    const float* x_a        = (const float*)d_in[0];
    const void*  edge_index =               d_in[1];
    const float* edge_attr  = (const float*)d_in[2];
    const float* g_w        = (const float*)d_in[3];
    const float* g_b        = (const float*)d_in[4];
    const float* f_w        = (const float*)d_in[5];
    const float* f_b        = (const float*)d_in[6];
    const float* cls_w      = (const float*)d_in[7];
    const float* cls_b      = (const float*)d_in[8];
    float* out = (float*)d_out;

    int       N = in_sizes[0] / C;        // 20000
    long long E = (long long)in_sizes[2]; // 640000
    int twopart = (out_size >= 2 * N) ? 1 : 0;

    pre_kernel<<<P_NBLK, P_NTHR>>>(x_a, g_w, g_b, f_w, f_b, cls_w, cls_b, N);

    {   // edge kernel: 2 edges/thread
        long long pairs = E >> 1;
        dim3 grid((unsigned)((pairs + E_NTHR - 1) / E_NTHR));
        void* args[] = {(void*)&edge_index, (void*)&edge_attr, (void*)&E};
        launch_pdl((const void*)edge_kernel, grid, dim3(E_NTHR), args);
    }
    {   // out kernel
        dim3 grid((N + O_NTHR - 1) / O_NTHR);
        void* args[] = {(void*)&out, (void*)&N, (void*)&twopart};
        launch_pdl((const void*)out_kernel, grid, dim3(O_NTHR), args);
    }
}